// round 1
// baseline (speedup 1.0000x reference)
#include <cuda_runtime.h>
#include <math.h>

#define N_HALF 4096
#define N_TOT  8192
#define DIM    512
#define TILE   128
#define BK     16
#define GRID_T (N_TOT / TILE)                 // 64
#define NUM_TILES (GRID_T * (GRID_T + 1) / 2) // 2080

__device__ float g_sq[N_TOT];
__device__ float g_colsum[DIM];
__device__ float g_coef;               // -log2(e) / (4*bandwidth)
__device__ float g_partials[NUM_TILES];

__device__ __forceinline__ const float* row_ptr(const float* __restrict__ src,
                                                const float* __restrict__ tgt, int r) {
    return (r < N_HALF) ? (src + (size_t)r * DIM) : (tgt + (size_t)(r - N_HALF) * DIM);
}

// --- column sums (for analytic sum(L2)) ---
__global__ void colsum_kernel(const float* __restrict__ src, const float* __restrict__ tgt) {
    int d = blockIdx.x * blockDim.x + threadIdx.x;
    if (d >= DIM) return;
    float s = 0.f;
    for (int r = 0; r < N_HALF; r++) s += src[(size_t)r * DIM + d];
    for (int r = 0; r < N_HALF; r++) s += tgt[(size_t)r * DIM + d];
    g_colsum[d] = s;
}

// --- per-row squared norms (one warp per row) ---
__global__ void rowsq_kernel(const float* __restrict__ src, const float* __restrict__ tgt) {
    int warp = (blockIdx.x * blockDim.x + threadIdx.x) >> 5;
    int lane = threadIdx.x & 31;
    if (warp >= N_TOT) return;
    const float4* p4 = (const float4*)row_ptr(src, tgt, warp);
    float s = 0.f;
#pragma unroll
    for (int i = 0; i < DIM / 4 / 32; i++) {
        float4 v = p4[lane + i * 32];
        s += v.x * v.x + v.y * v.y + v.z * v.z + v.w * v.w;
    }
#pragma unroll
    for (int o = 16; o; o >>= 1) s += __shfl_xor_sync(0xffffffffu, s, o);
    if (lane == 0) g_sq[warp] = s;
}

// --- bandwidth: sum(L2) = 2N*sum(sq) - 2*||colsum||^2 ---
__global__ void bw_kernel() {
    __shared__ double sh[256];
    int t = threadIdx.x;
    double acc = 0.0;
    for (int i = t; i < N_TOT; i += 256) acc += (double)g_sq[i];
    double acc2 = 0.0;
    for (int i = t; i < DIM; i += 256) { double c = (double)g_colsum[i]; acc2 += c * c; }
    sh[t] = acc; __syncthreads();
    for (int o = 128; o; o >>= 1) { if (t < o) sh[t] += sh[t + o]; __syncthreads(); }
    double sumsq = sh[0];
    __syncthreads();
    sh[t] = acc2; __syncthreads();
    for (int o = 128; o; o >>= 1) { if (t < o) sh[t] += sh[t + o]; __syncthreads(); }
    if (t == 0) {
        double ss = sh[0];
        double sumL2 = 2.0 * (double)N_TOT * sumsq - 2.0 * ss;
        double bw = sumL2 / ((double)N_TOT * (double)N_TOT - (double)N_TOT);
        // t = exp(-L2/(4*bw)) = exp2(L2 * coef); kernels = t + t^2 + t^4 + t^8 + t^16
        g_coef = (float)(-1.4426950408889634 / (4.0 * bw));
    }
}

// --- fused gram + RBF-mixture + signed partial sum, upper-triangular tiles ---
__global__ __launch_bounds__(256) void mmd_kernel(const float* __restrict__ src,
                                                  const float* __restrict__ tgt) {
    // map blockIdx.x -> (ti, tj) with tj >= ti
    int rem = blockIdx.x;
    int ti = 0;
    while (rem >= GRID_T - ti) { rem -= GRID_T - ti; ti++; }
    int tj = ti + rem;

    __shared__ float As[BK][TILE + 4];
    __shared__ float Bs[BK][TILE + 4];
    __shared__ float sqA[TILE];
    __shared__ float sqB[TILE];
    __shared__ float red[256];

    int tid = threadIdx.x;
    int tx = tid & 15;   // 0..15 -> 8 cols
    int ty = tid >> 4;   // 0..15 -> 8 rows

    int rowA0 = ti * TILE;
    int rowB0 = tj * TILE;

    if (tid < TILE) sqA[tid] = g_sq[rowA0 + tid];
    else            sqB[tid - TILE] = g_sq[rowB0 + (tid - TILE)];

    float acc[8][8];
#pragma unroll
    for (int i = 0; i < 8; i++)
#pragma unroll
        for (int j = 0; j < 8; j++) acc[i][j] = 0.f;

    // loader mapping: 2 float4 per operand per chunk per thread
    int lr = tid >> 2;  // 0..63
    int lc = tid & 3;   // float4 index within BK=16

    for (int k0 = 0; k0 < DIM; k0 += BK) {
#pragma unroll
        for (int p = 0; p < 2; p++) {
            int r = lr + p * 64;
            const float* pa = row_ptr(src, tgt, rowA0 + r);
            float4 v = *(const float4*)(pa + k0 + lc * 4);
            As[lc * 4 + 0][r] = v.x; As[lc * 4 + 1][r] = v.y;
            As[lc * 4 + 2][r] = v.z; As[lc * 4 + 3][r] = v.w;
            const float* pb = row_ptr(src, tgt, rowB0 + r);
            float4 w = *(const float4*)(pb + k0 + lc * 4);
            Bs[lc * 4 + 0][r] = w.x; Bs[lc * 4 + 1][r] = w.y;
            Bs[lc * 4 + 2][r] = w.z; Bs[lc * 4 + 3][r] = w.w;
        }
        __syncthreads();
#pragma unroll
        for (int k = 0; k < BK; k++) {
            float a[8], b[8];
#pragma unroll
            for (int i = 0; i < 8; i++) a[i] = As[k][ty * 8 + i];
#pragma unroll
            for (int j = 0; j < 8; j++) b[j] = Bs[k][tx * 8 + j];
#pragma unroll
            for (int i = 0; i < 8; i++)
#pragma unroll
                for (int j = 0; j < 8; j++) acc[i][j] += a[i] * b[j];
        }
        __syncthreads();
    }

    float coef = g_coef;
    float part = 0.f;
#pragma unroll
    for (int i = 0; i < 8; i++) {
        float si = sqA[ty * 8 + i];
#pragma unroll
        for (int j = 0; j < 8; j++) {
            float L2 = si + sqB[tx * 8 + j] - 2.f * acc[i][j];
            float t;
            asm("ex2.approx.ftz.f32 %0, %1;" : "=f"(t) : "f"(L2 * coef));
            float t2 = t * t, t4 = t2 * t2, t8 = t4 * t4, t16 = t8 * t8;
            part += t + t2 + t4 + t8 + t16;
        }
    }

    red[tid] = part; __syncthreads();
#pragma unroll
    for (int o = 128; o; o >>= 1) { if (tid < o) red[tid] += red[tid + o]; __syncthreads(); }
    if (tid == 0) {
        float sign = ((ti < GRID_T / 2) == (tj < GRID_T / 2)) ? 1.f : -1.f;
        float wgt = (ti == tj) ? 1.f : 2.f;
        g_partials[blockIdx.x] = red[0] * sign * wgt;
    }
}

__global__ void reduce_kernel(float* __restrict__ out) {
    __shared__ double sh[256];
    int t = threadIdx.x;
    double a = 0.0;
    for (int i = t; i < NUM_TILES; i += 256) a += (double)g_partials[i];
    sh[t] = a; __syncthreads();
    for (int o = 128; o; o >>= 1) { if (t < o) sh[t] += sh[t + o]; __syncthreads(); }
    if (t == 0) out[0] = (float)(sh[0] / ((double)N_HALF * (double)N_HALF));
}

extern "C" void kernel_launch(void* const* d_in, const int* in_sizes, int n_in,
                              void* d_out, int out_size) {
    const float* src = (const float*)d_in[0];
    const float* tgt = (const float*)d_in[1];
    colsum_kernel<<<4, 128>>>(src, tgt);
    rowsq_kernel<<<N_TOT / 8, 256>>>(src, tgt);
    bw_kernel<<<1, 256>>>();
    mmd_kernel<<<NUM_TILES, 256>>>(src, tgt);
    reduce_kernel<<<1, 256>>>((float*)d_out);
}

// round 3
// speedup vs baseline: 3.0296x; 3.0296x over previous
#include <cuda_runtime.h>
#include <cuda_bf16.h>
#include <stdint.h>

#define N_HALF 4096
#define N_TOT  8192
#define DIM    512
#define TILE   128
#define KC     64
#define NCHUNK 8
#define GRID_T 64
#define NUM_TILES 2080

__device__ __nv_bfloat16 g_hi[(size_t)N_TOT * DIM];
__device__ __nv_bfloat16 g_lo[(size_t)N_TOT * DIM];
__device__ float g_sq[N_TOT];
__device__ float g_colsum[DIM];
__device__ float g_coef;
__device__ float g_partials[NUM_TILES];

__device__ __forceinline__ uint32_t smem_u32_of(const void* p) {
    uint32_t a;
    asm("{ .reg .u64 t; cvta.to.shared.u64 t, %1; cvt.u32.u64 %0, t; }" : "=r"(a) : "l"(p));
    return a;
}

#define LDSM_X4(r, addr)                                                       \
    asm volatile("ldmatrix.sync.aligned.m8n8.x4.shared.b16 {%0,%1,%2,%3}, [%4];" \
        : "=r"((r)[0]), "=r"((r)[1]), "=r"((r)[2]), "=r"((r)[3]) : "r"(addr))

#define MMA_BF16(c, a, b0, b1)                                                 \
    asm volatile("mma.sync.aligned.m16n8k16.row.col.f32.bf16.bf16.f32 "        \
        "{%0,%1,%2,%3},{%4,%5,%6,%7},{%8,%9},{%0,%1,%2,%3};"                   \
        : "+f"((c)[0]), "+f"((c)[1]), "+f"((c)[2]), "+f"((c)[3])               \
        : "r"((a)[0]), "r"((a)[1]), "r"((a)[2]), "r"((a)[3]), "r"(b0), "r"(b1))

// ---------------- smem map (bytes) ----------------
#define SM_TILE    16384              // one 128x64 bf16 tile
#define SM_STAGE   65536              // Ahi, Alo, Bhi, Blo
#define SM_SQA     131072
#define SM_SQB     (SM_SQA + 512)
#define SM_RED     (SM_SQB + 512)
#define SMEM_TOTAL (SM_RED + 1024)

// ---------------- preprocess ----------------
__global__ void zero_colsum_kernel() {
    int i = blockIdx.x * blockDim.x + threadIdx.x;
    if (i < DIM) g_colsum[i] = 0.f;
}

__global__ __launch_bounds__(256) void prep_kernel(const float* __restrict__ src,
                                                   const float* __restrict__ tgt) {
    __shared__ float cs[DIM];
    int tid = threadIdx.x;
    for (int i = tid; i < DIM; i += 256) cs[i] = 0.f;
    __syncthreads();
    int warp = tid >> 5, lane = tid & 31;
    int row = blockIdx.x * 8 + warp;
    const float* p = (row < N_HALF) ? src + (size_t)row * DIM
                                    : tgt + (size_t)(row - N_HALF) * DIM;
    const float2* p2 = (const float2*)p;
    __nv_bfloat162* h2p = (__nv_bfloat162*)(g_hi + (size_t)row * DIM);
    __nv_bfloat162* l2p = (__nv_bfloat162*)(g_lo + (size_t)row * DIM);
    float sq = 0.f;
#pragma unroll
    for (int i = 0; i < 8; i++) {
        int c = lane + 32 * i;
        float2 v = p2[c];
        sq += v.x * v.x + v.y * v.y;
        atomicAdd(&cs[2 * c], v.x);
        atomicAdd(&cs[2 * c + 1], v.y);
        __nv_bfloat16 hx = __float2bfloat16(v.x);
        __nv_bfloat16 hy = __float2bfloat16(v.y);
        __nv_bfloat162 h2; h2.x = hx; h2.y = hy;
        __nv_bfloat162 l2;
        l2.x = __float2bfloat16(v.x - __bfloat162float(hx));
        l2.y = __float2bfloat16(v.y - __bfloat162float(hy));
        h2p[c] = h2;
        l2p[c] = l2;
    }
#pragma unroll
    for (int o = 16; o; o >>= 1) sq += __shfl_xor_sync(0xffffffffu, sq, o);
    if (lane == 0) g_sq[row] = sq;
    __syncthreads();
    for (int i = tid; i < DIM; i += 256) atomicAdd(&g_colsum[i], cs[i]);
}

__global__ void bw_kernel() {
    __shared__ double sh[256];
    int t = threadIdx.x;
    double acc = 0.0;
    for (int i = t; i < N_TOT; i += 256) acc += (double)g_sq[i];
    double acc2 = 0.0;
    for (int i = t; i < DIM; i += 256) { double c = (double)g_colsum[i]; acc2 += c * c; }
    sh[t] = acc; __syncthreads();
    for (int o = 128; o; o >>= 1) { if (t < o) sh[t] += sh[t + o]; __syncthreads(); }
    double sumsq = sh[0];
    __syncthreads();
    sh[t] = acc2; __syncthreads();
    for (int o = 128; o; o >>= 1) { if (t < o) sh[t] += sh[t + o]; __syncthreads(); }
    if (t == 0) {
        double ss = sh[0];
        double sumL2 = 2.0 * (double)N_TOT * sumsq - 2.0 * ss;
        double bw = sumL2 / ((double)N_TOT * (double)N_TOT - (double)N_TOT);
        g_coef = (float)(-1.4426950408889634 / (4.0 * bw));
    }
}

// ---------------- async tile loader ----------------
__device__ __forceinline__ void load_chunk_async(uint32_t sbase, uint32_t stage, int c,
                                                 int rowA0, int rowB0, int tid) {
#pragma unroll
    for (int m = 0; m < 16; m++) {
        int u = tid + 256 * m;
        int t = u >> 10;            // 0..3: Ahi, Alo, Bhi, Blo
        int v = u & 1023;
        int r = v >> 3;             // row 0..127
        int i16 = v & 7;            // 16B group within 128B row
        int grow = ((t < 2) ? rowA0 : rowB0) + r;
        const __nv_bfloat16* base = (t & 1) ? g_lo : g_hi;
        const char* gp = (const char*)(base + (size_t)grow * DIM) + c * 128 + i16 * 16;
        uint32_t dst = sbase + stage * SM_STAGE + (uint32_t)t * SM_TILE
                     + (uint32_t)(r * 128) + (uint32_t)((i16 ^ (r & 7)) << 4);
        asm volatile("cp.async.cg.shared.global [%0], [%1], 16;" :: "r"(dst), "l"(gp));
    }
}

// ---------------- fused gram (HMMA) + RBF mixture ----------------
__global__ __launch_bounds__(256, 1) void mmd_mma_kernel() {
    extern __shared__ char smem[];
    const uint32_t sbase = smem_u32_of(smem);
    int tid = threadIdx.x;
    int wid = tid >> 5, lane = tid & 31;

    int rem = blockIdx.x, ti = 0;
    while (rem >= GRID_T - ti) { rem -= GRID_T - ti; ti++; }
    int tj = ti + rem;
    int rowA0 = ti * TILE, rowB0 = tj * TILE;

    float* sqA_s = (float*)(smem + SM_SQA);
    float* sqB_s = (float*)(smem + SM_SQB);
    if (tid < 128) sqA_s[tid] = g_sq[rowA0 + tid];
    else           sqB_s[tid - 128] = g_sq[rowB0 + (tid - 128)];

    // prologue: chunks 0,1
    load_chunk_async(sbase, 0, 0, rowA0, rowB0, tid);
    asm volatile("cp.async.commit_group;" ::: "memory");
    load_chunk_async(sbase, 1, 1, rowA0, rowB0, tid);
    asm volatile("cp.async.commit_group;" ::: "memory");

    // warp tiling: 2 (rows) x 4 (cols) warps; warp tile 64x32
    int wr = wid >> 2, wc = wid & 3;
    int rA = wr * 64 + (lane & 15);
    int kgA = lane >> 4;
    int xrA = rA & 7;
    uint32_t aAddr[4];
#pragma unroll
    for (int mi = 0; mi < 4; mi++)
        aAddr[mi] = sbase + (uint32_t)((rA + mi * 16) * 128);
    int nB = wc * 32 + (lane & 7) + ((lane >> 4) << 3);
    int kgB = (lane >> 3) & 1;
    int xrB = nB & 7;
    uint32_t bAddr[2];
#pragma unroll
    for (int nb = 0; nb < 2; nb++)
        bAddr[nb] = sbase + 2u * SM_TILE + (uint32_t)((nB + nb * 16) * 128);

    float acc[4][4][4];
#pragma unroll
    for (int i = 0; i < 4; i++)
#pragma unroll
        for (int j = 0; j < 4; j++)
#pragma unroll
            for (int e = 0; e < 4; e++) acc[i][j][e] = 0.f;

    for (int c = 0; c < NCHUNK; c++) {
        if (c < NCHUNK - 1) asm volatile("cp.async.wait_group 1;" ::: "memory");
        else                asm volatile("cp.async.wait_group 0;" ::: "memory");
        __syncthreads();
        uint32_t stoff = (uint32_t)(c & 1) * SM_STAGE;
#pragma unroll
        for (int s = 0; s < 4; s++) {
            uint32_t colA = (uint32_t)(((s * 2 + kgA) ^ xrA) << 4);
            uint32_t colB = (uint32_t)(((s * 2 + kgB) ^ xrB) << 4);
            uint32_t ah[4][4], al[4][4], bh[2][4], bl[2][4];
#pragma unroll
            for (int mi = 0; mi < 4; mi++) {
                LDSM_X4(ah[mi], aAddr[mi] + stoff + colA);
                LDSM_X4(al[mi], aAddr[mi] + stoff + colA + SM_TILE);
            }
#pragma unroll
            for (int nb = 0; nb < 2; nb++) {
                LDSM_X4(bh[nb], bAddr[nb] + stoff + colB);
                LDSM_X4(bl[nb], bAddr[nb] + stoff + colB + SM_TILE);
            }
#pragma unroll
            for (int mi = 0; mi < 4; mi++) {
#pragma unroll
                for (int ni = 0; ni < 4; ni++) {
                    int nb = ni >> 1, j = ni & 1;
                    MMA_BF16(acc[mi][ni], ah[mi], bh[nb][2 * j], bh[nb][2 * j + 1]);
                    MMA_BF16(acc[mi][ni], ah[mi], bl[nb][2 * j], bl[nb][2 * j + 1]);
                    MMA_BF16(acc[mi][ni], al[mi], bh[nb][2 * j], bh[nb][2 * j + 1]);
                }
            }
        }
        __syncthreads();
        if (c + 2 < NCHUNK) {
            load_chunk_async(sbase, (uint32_t)(c & 1), c + 2, rowA0, rowB0, tid);
            asm volatile("cp.async.commit_group;" ::: "memory");
        }
    }

    // epilogue: RBF mixture from register accumulators
    float coef = g_coef;
    float part = 0.f;
    int re = wr * 64 + (lane >> 2);
    int ce = wc * 32 + (lane & 3) * 2;
#pragma unroll
    for (int mi = 0; mi < 4; mi++) {
#pragma unroll
        for (int ni = 0; ni < 4; ni++) {
            int row = re + mi * 16;
            int col = ce + ni * 8;
#pragma unroll
            for (int e = 0; e < 4; e++) {
                float sA = sqA_s[row + ((e >> 1) << 3)];
                float sB = sqB_s[col + (e & 1)];
                float L2 = sA + sB - 2.f * acc[mi][ni][e];
                float t;
                asm("ex2.approx.ftz.f32 %0, %1;" : "=f"(t) : "f"(L2 * coef));
                float t2 = t * t, t4 = t2 * t2, t8 = t4 * t4, t16 = t8 * t8;
                part += t + t2 + t4 + t8 + t16;
            }
        }
    }

    float* red = (float*)(smem + SM_RED);
    red[tid] = part;
    __syncthreads();
#pragma unroll
    for (int o = 128; o; o >>= 1) {
        if (tid < o) red[tid] += red[tid + o];
        __syncthreads();
    }
    if (tid == 0) {
        float sign = ((ti < GRID_T / 2) == (tj < GRID_T / 2)) ? 1.f : -1.f;
        float wgt = (ti == tj) ? 1.f : 2.f;
        g_partials[blockIdx.x] = red[0] * sign * wgt;
    }
}

__global__ void reduce_kernel(float* __restrict__ out) {
    __shared__ double sh[256];
    int t = threadIdx.x;
    double a = 0.0;
    for (int i = t; i < NUM_TILES; i += 256) a += (double)g_partials[i];
    sh[t] = a; __syncthreads();
    for (int o = 128; o; o >>= 1) { if (t < o) sh[t] += sh[t + o]; __syncthreads(); }
    if (t == 0) out[0] = (float)(sh[0] / ((double)N_HALF * (double)N_HALF));
}

extern "C" void kernel_launch(void* const* d_in, const int* in_sizes, int n_in,
                              void* d_out, int out_size) {
    const float* src = (const float*)d_in[0];
    const float* tgt = (const float*)d_in[1];
    cudaFuncSetAttribute(mmd_mma_kernel, cudaFuncAttributeMaxDynamicSharedMemorySize,
                         SMEM_TOTAL);
    zero_colsum_kernel<<<2, 256>>>();
    prep_kernel<<<N_TOT / 8, 256>>>(src, tgt);
    bw_kernel<<<1, 256>>>();
    mmd_mma_kernel<<<NUM_TILES, 256, SMEM_TOTAL>>>();
    reduce_kernel<<<1, 256>>>((float*)d_out);
}

// round 4
// speedup vs baseline: 3.8330x; 1.2652x over previous
#include <cuda_runtime.h>
#include <cuda_bf16.h>
#include <stdint.h>

#define N_HALF 4096
#define N_TOT  8192
#define DIM    512
#define TILE   128
#define NCHUNK 8
#define GRID_T 64
#define NUM_TILES 2080

__device__ __nv_bfloat16 g_hi[(size_t)N_TOT * DIM];
__device__ __nv_bfloat16 g_lo[(size_t)N_TOT * DIM];
__device__ float g_sq[N_TOT];
__device__ float g_colsum[DIM];
__device__ float g_coef;
__device__ float g_partials[NUM_TILES];

__device__ __forceinline__ uint32_t smem_u32_of(const void* p) {
    uint32_t a;
    asm("{ .reg .u64 t; cvta.to.shared.u64 t, %1; cvt.u32.u64 %0, t; }" : "=r"(a) : "l"(p));
    return a;
}

#define LDSM_X4(r, addr)                                                       \
    asm volatile("ldmatrix.sync.aligned.m8n8.x4.shared.b16 {%0,%1,%2,%3}, [%4];" \
        : "=r"((r)[0]), "=r"((r)[1]), "=r"((r)[2]), "=r"((r)[3]) : "r"(addr))

#define MMA_BF16(c, a, b0, b1)                                                 \
    asm volatile("mma.sync.aligned.m16n8k16.row.col.f32.bf16.bf16.f32 "        \
        "{%0,%1,%2,%3},{%4,%5,%6,%7},{%8,%9},{%0,%1,%2,%3};"                   \
        : "+f"((c)[0]), "+f"((c)[1]), "+f"((c)[2]), "+f"((c)[3])               \
        : "r"((a)[0]), "r"((a)[1]), "r"((a)[2]), "r"((a)[3]), "r"(b0), "r"(b1))

// ---------------- smem map (bytes) ----------------
// per stage: Ahi (16K) | Bhi (16K) | Blo (16K) = 48K; 3 stages
#define SM_TILE    16384
#define SM_STAGE   49152
#define SM_SQA     147456
#define SM_SQB     (SM_SQA + 512)
#define SM_RED     (SM_SQB + 512)
#define SMEM_TOTAL (SM_RED + 2048)

// ---------------- preprocess ----------------
__global__ void zero_colsum_kernel() {
    int i = blockIdx.x * blockDim.x + threadIdx.x;
    if (i < DIM) g_colsum[i] = 0.f;
}

__global__ __launch_bounds__(256) void prep_kernel(const float* __restrict__ src,
                                                   const float* __restrict__ tgt) {
    __shared__ float cs[DIM];
    int tid = threadIdx.x;
    for (int i = tid; i < DIM; i += 256) cs[i] = 0.f;
    __syncthreads();
    int warp = tid >> 5, lane = tid & 31;
    int row = blockIdx.x * 8 + warp;
    const float* p = (row < N_HALF) ? src + (size_t)row * DIM
                                    : tgt + (size_t)(row - N_HALF) * DIM;
    const float2* p2 = (const float2*)p;
    __nv_bfloat162* h2p = (__nv_bfloat162*)(g_hi + (size_t)row * DIM);
    __nv_bfloat162* l2p = (__nv_bfloat162*)(g_lo + (size_t)row * DIM);
    float sq = 0.f;
#pragma unroll
    for (int i = 0; i < 8; i++) {
        int c = lane + 32 * i;
        float2 v = p2[c];
        sq += v.x * v.x + v.y * v.y;
        atomicAdd(&cs[2 * c], v.x);
        atomicAdd(&cs[2 * c + 1], v.y);
        __nv_bfloat16 hx = __float2bfloat16(v.x);
        __nv_bfloat16 hy = __float2bfloat16(v.y);
        __nv_bfloat162 h2; h2.x = hx; h2.y = hy;
        __nv_bfloat162 l2;
        l2.x = __float2bfloat16(v.x - __bfloat162float(hx));
        l2.y = __float2bfloat16(v.y - __bfloat162float(hy));
        h2p[c] = h2;
        l2p[c] = l2;
    }
#pragma unroll
    for (int o = 16; o; o >>= 1) sq += __shfl_xor_sync(0xffffffffu, sq, o);
    if (lane == 0) g_sq[row] = sq;
    __syncthreads();
    for (int i = tid; i < DIM; i += 256) atomicAdd(&g_colsum[i], cs[i]);
}

__global__ void bw_kernel() {
    __shared__ double sh[256];
    int t = threadIdx.x;
    double acc = 0.0;
    for (int i = t; i < N_TOT; i += 256) acc += (double)g_sq[i];
    double acc2 = 0.0;
    for (int i = t; i < DIM; i += 256) { double c = (double)g_colsum[i]; acc2 += c * c; }
    sh[t] = acc; __syncthreads();
    for (int o = 128; o; o >>= 1) { if (t < o) sh[t] += sh[t + o]; __syncthreads(); }
    double sumsq = sh[0];
    __syncthreads();
    sh[t] = acc2; __syncthreads();
    for (int o = 128; o; o >>= 1) { if (t < o) sh[t] += sh[t + o]; __syncthreads(); }
    if (t == 0) {
        double ss = sh[0];
        double sumL2 = 2.0 * (double)N_TOT * sumsq - 2.0 * ss;
        double bw = sumL2 / ((double)N_TOT * (double)N_TOT - (double)N_TOT);
        g_coef = (float)(-1.4426950408889634 / (4.0 * bw));
    }
}

// ---------------- async tile loader (3 tiles: Ahi, Bhi, Blo) ----------------
__device__ __forceinline__ void load_chunk_async(uint32_t sbase, uint32_t stage, int c,
                                                 int rowA0, int rowB0, int tid) {
#pragma unroll
    for (int m = 0; m < 6; m++) {
        int u = tid + 512 * m;
        int t = u >> 10;            // 0: Ahi, 1: Bhi, 2: Blo
        int v = u & 1023;
        int r = v >> 3;             // row 0..127
        int i16 = v & 7;            // 16B group within 128B row
        int grow = ((t == 0) ? rowA0 : rowB0) + r;
        const __nv_bfloat16* base = (t == 2) ? g_lo : g_hi;
        const char* gp = (const char*)(base + (size_t)grow * DIM) + c * 128 + i16 * 16;
        uint32_t dst = sbase + stage * SM_STAGE + (uint32_t)t * SM_TILE
                     + (uint32_t)(r * 128) + (uint32_t)((i16 ^ (r & 7)) << 4);
        asm volatile("cp.async.cg.shared.global [%0], [%1], 16;" :: "r"(dst), "l"(gp));
    }
}

// ---------------- fused gram (HMMA, 2-product bf16 split) + RBF mixture ----------------
__global__ __launch_bounds__(512, 1) void mmd_mma_kernel() {
    extern __shared__ char smem[];
    const uint32_t sbase = smem_u32_of(smem);
    int tid = threadIdx.x;
    int wid = tid >> 5, lane = tid & 31;

    int rem = blockIdx.x, ti = 0;
    while (rem >= GRID_T - ti) { rem -= GRID_T - ti; ti++; }
    int tj = ti + rem;
    int rowA0 = ti * TILE, rowB0 = tj * TILE;

    float* sqA_s = (float*)(smem + SM_SQA);
    float* sqB_s = (float*)(smem + SM_SQB);
    if (tid < 128)      sqA_s[tid] = g_sq[rowA0 + tid];
    else if (tid < 256) sqB_s[tid - 128] = g_sq[rowB0 + (tid - 128)];

    // prologue: chunks 0,1 -> stages 0,1
    load_chunk_async(sbase, 0, 0, rowA0, rowB0, tid);
    asm volatile("cp.async.commit_group;" ::: "memory");
    load_chunk_async(sbase, 1, 1, rowA0, rowB0, tid);
    asm volatile("cp.async.commit_group;" ::: "memory");

    // warp tiling: 4 (rows) x 4 (cols) warps; warp tile 32x32
    int wr = wid >> 2, wc = wid & 3;
    int rA = wr * 32 + (lane & 15);
    int kgA = lane >> 4;
    int xrA = rA & 7;
    uint32_t aAddr[2];
#pragma unroll
    for (int mi = 0; mi < 2; mi++)
        aAddr[mi] = sbase + (uint32_t)((rA + mi * 16) * 128);
    int nB = wc * 32 + (lane & 7) + ((lane >> 4) << 3);
    int kgB = (lane >> 3) & 1;
    int xrB = nB & 7;
    uint32_t bAddr[2];
#pragma unroll
    for (int nb = 0; nb < 2; nb++)
        bAddr[nb] = sbase + SM_TILE + (uint32_t)((nB + nb * 16) * 128);

    float acc[2][4][4];
#pragma unroll
    for (int i = 0; i < 2; i++)
#pragma unroll
        for (int j = 0; j < 4; j++)
#pragma unroll
            for (int e = 0; e < 4; e++) acc[i][j][e] = 0.f;

    int stage = 0;
    for (int c = 0; c < NCHUNK; c++) {
        if (c + 2 < NCHUNK) asm volatile("cp.async.wait_group 1;" ::: "memory");
        else                asm volatile("cp.async.wait_group 0;" ::: "memory");
        __syncthreads();
        // stage (c+2)%3 was freed by compute of chunk c-1 (proven by the sync above)
        if (c + 2 < NCHUNK) {
            int sn = stage + 2; if (sn >= 3) sn -= 3;
            load_chunk_async(sbase, (uint32_t)sn, c + 2, rowA0, rowB0, tid);
            asm volatile("cp.async.commit_group;" ::: "memory");
        }
        uint32_t stoff = (uint32_t)stage * SM_STAGE;
#pragma unroll
        for (int s = 0; s < 4; s++) {
            uint32_t colA = (uint32_t)(((s * 2 + kgA) ^ xrA) << 4);
            uint32_t colB = (uint32_t)(((s * 2 + kgB) ^ xrB) << 4);
            uint32_t ah[2][4], bh[2][4], bl[2][4];
#pragma unroll
            for (int mi = 0; mi < 2; mi++)
                LDSM_X4(ah[mi], aAddr[mi] + stoff + colA);
#pragma unroll
            for (int nb = 0; nb < 2; nb++) {
                LDSM_X4(bh[nb], bAddr[nb] + stoff + colB);
                LDSM_X4(bl[nb], bAddr[nb] + stoff + colB + SM_TILE);
            }
#pragma unroll
            for (int mi = 0; mi < 2; mi++) {
#pragma unroll
                for (int ni = 0; ni < 4; ni++) {
                    int nb = ni >> 1, j = ni & 1;
                    MMA_BF16(acc[mi][ni], ah[mi], bh[nb][2 * j], bh[nb][2 * j + 1]);
                    MMA_BF16(acc[mi][ni], ah[mi], bl[nb][2 * j], bl[nb][2 * j + 1]);
                }
            }
        }
        stage++; if (stage >= 3) stage = 0;
    }

    // epilogue: RBF mixture from register accumulators
    float coef = g_coef;
    float part = 0.f;
    int re = wr * 32 + (lane >> 2);
    int ce = wc * 32 + (lane & 3) * 2;
#pragma unroll
    for (int mi = 0; mi < 2; mi++) {
#pragma unroll
        for (int ni = 0; ni < 4; ni++) {
            int row = re + mi * 16;
            int col = ce + ni * 8;
#pragma unroll
            for (int e = 0; e < 4; e++) {
                float sA = sqA_s[row + ((e >> 1) << 3)];
                float sB = sqB_s[col + (e & 1)];
                float L2 = sA + sB - 2.f * acc[mi][ni][e];
                float t;
                asm("ex2.approx.ftz.f32 %0, %1;" : "=f"(t) : "f"(L2 * coef));
                float t2 = t * t, t4 = t2 * t2, t8 = t4 * t4, t16 = t8 * t8;
                part += t + t2 + t4 + t8 + t16;
            }
        }
    }

    float* red = (float*)(smem + SM_RED);
    red[tid] = part;
    __syncthreads();
#pragma unroll
    for (int o = 256; o; o >>= 1) {
        if (tid < o) red[tid] += red[tid + o];
        __syncthreads();
    }
    if (tid == 0) {
        float sign = ((ti < GRID_T / 2) == (tj < GRID_T / 2)) ? 1.f : -1.f;
        float wgt = (ti == tj) ? 1.f : 2.f;
        g_partials[blockIdx.x] = red[0] * sign * wgt;
    }
}

__global__ void reduce_kernel(float* __restrict__ out) {
    __shared__ double sh[256];
    int t = threadIdx.x;
    double a = 0.0;
    for (int i = t; i < NUM_TILES; i += 256) a += (double)g_partials[i];
    sh[t] = a; __syncthreads();
    for (int o = 128; o; o >>= 1) { if (t < o) sh[t] += sh[t + o]; __syncthreads(); }
    if (t == 0) out[0] = (float)(sh[0] / ((double)N_HALF * (double)N_HALF));
}

extern "C" void kernel_launch(void* const* d_in, const int* in_sizes, int n_in,
                              void* d_out, int out_size) {
    const float* src = (const float*)d_in[0];
    const float* tgt = (const float*)d_in[1];
    cudaFuncSetAttribute(mmd_mma_kernel, cudaFuncAttributeMaxDynamicSharedMemorySize,
                         SMEM_TOTAL);
    zero_colsum_kernel<<<2, 256>>>();
    prep_kernel<<<N_TOT / 8, 256>>>(src, tgt);
    bw_kernel<<<1, 256>>>();
    mmd_mma_kernel<<<NUM_TILES, 512, SMEM_TOTAL>>>();
    reduce_kernel<<<1, 256>>>((float*)d_out);
}

// round 5
// speedup vs baseline: 4.3064x; 1.1235x over previous
#include <cuda_runtime.h>
#include <cuda_bf16.h>
#include <stdint.h>

#define N_HALF 4096
#define N_TOT  8192
#define DIM    512
#define TILE   128
#define NCHUNK 8
#define GRID_T 64
#define NUM_TILES 2080

__device__ __nv_bfloat16 g_hi[(size_t)N_TOT * DIM];
__device__ __nv_bfloat16 g_lo[(size_t)N_TOT * DIM];
__device__ float g_sq[N_TOT];
__device__ float g_colsum[DIM];
__device__ float g_coef;
__device__ float g_partials[NUM_TILES];

__device__ __forceinline__ uint32_t smem_u32_of(const void* p) {
    uint32_t a;
    asm("{ .reg .u64 t; cvta.to.shared.u64 t, %1; cvt.u32.u64 %0, t; }" : "=r"(a) : "l"(p));
    return a;
}

#define LDSM_X4(r, addr)                                                       \
    asm volatile("ldmatrix.sync.aligned.m8n8.x4.shared.b16 {%0,%1,%2,%3}, [%4];" \
        : "=r"((r)[0]), "=r"((r)[1]), "=r"((r)[2]), "=r"((r)[3]) : "r"(addr))

#define MMA_BF16(c, a, b0, b1)                                                 \
    asm volatile("mma.sync.aligned.m16n8k16.row.col.f32.bf16.bf16.f32 "        \
        "{%0,%1,%2,%3},{%4,%5,%6,%7},{%8,%9},{%0,%1,%2,%3};"                   \
        : "+f"((c)[0]), "+f"((c)[1]), "+f"((c)[2]), "+f"((c)[3])               \
        : "r"((a)[0]), "r"((a)[1]), "r"((a)[2]), "r"((a)[3]), "r"(b0), "r"(b1))

// ---------------- smem map (bytes) ----------------
// per stage: Ahi (16K) | Bhi (16K) | Blo (16K) = 48K; 2 stages (2 CTAs/SM)
#define SM_TILE    16384
#define SM_STAGE   49152
#define SM_SQA     98304
#define SM_SQB     (SM_SQA + 512)
#define SM_RED     (SM_SQB + 512)
#define SMEM_TOTAL (SM_RED + 1024)

// ---------------- preprocess ----------------
__global__ void zero_colsum_kernel() {
    int i = blockIdx.x * blockDim.x + threadIdx.x;
    if (i < DIM) g_colsum[i] = 0.f;
}

__global__ __launch_bounds__(256) void prep_kernel(const float* __restrict__ src,
                                                   const float* __restrict__ tgt) {
    __shared__ float cs[DIM];
    int tid = threadIdx.x;
    for (int i = tid; i < DIM; i += 256) cs[i] = 0.f;
    __syncthreads();
    int warp = tid >> 5, lane = tid & 31;
    int row = blockIdx.x * 8 + warp;
    const float* p = (row < N_HALF) ? src + (size_t)row * DIM
                                    : tgt + (size_t)(row - N_HALF) * DIM;
    const float2* p2 = (const float2*)p;
    __nv_bfloat162* h2p = (__nv_bfloat162*)(g_hi + (size_t)row * DIM);
    __nv_bfloat162* l2p = (__nv_bfloat162*)(g_lo + (size_t)row * DIM);
    float sq = 0.f;
#pragma unroll
    for (int i = 0; i < 8; i++) {
        int c = lane + 32 * i;
        float2 v = p2[c];
        sq += v.x * v.x + v.y * v.y;
        atomicAdd(&cs[2 * c], v.x);
        atomicAdd(&cs[2 * c + 1], v.y);
        __nv_bfloat16 hx = __float2bfloat16(v.x);
        __nv_bfloat16 hy = __float2bfloat16(v.y);
        __nv_bfloat162 h2; h2.x = hx; h2.y = hy;
        __nv_bfloat162 l2;
        l2.x = __float2bfloat16(v.x - __bfloat162float(hx));
        l2.y = __float2bfloat16(v.y - __bfloat162float(hy));
        h2p[c] = h2;
        l2p[c] = l2;
    }
#pragma unroll
    for (int o = 16; o; o >>= 1) sq += __shfl_xor_sync(0xffffffffu, sq, o);
    if (lane == 0) g_sq[row] = sq;
    __syncthreads();
    for (int i = tid; i < DIM; i += 256) atomicAdd(&g_colsum[i], cs[i]);
}

__global__ void bw_kernel() {
    __shared__ double sh[256];
    int t = threadIdx.x;
    double acc = 0.0;
    for (int i = t; i < N_TOT; i += 256) acc += (double)g_sq[i];
    double acc2 = 0.0;
    for (int i = t; i < DIM; i += 256) { double c = (double)g_colsum[i]; acc2 += c * c; }
    sh[t] = acc; __syncthreads();
    for (int o = 128; o; o >>= 1) { if (t < o) sh[t] += sh[t + o]; __syncthreads(); }
    double sumsq = sh[0];
    __syncthreads();
    sh[t] = acc2; __syncthreads();
    for (int o = 128; o; o >>= 1) { if (t < o) sh[t] += sh[t + o]; __syncthreads(); }
    if (t == 0) {
        double ss = sh[0];
        double sumL2 = 2.0 * (double)N_TOT * sumsq - 2.0 * ss;
        double bw = sumL2 / ((double)N_TOT * (double)N_TOT - (double)N_TOT);
        g_coef = (float)(-1.4426950408889634 / (4.0 * bw));
    }
}

// ---------------- async tile loader (3 tiles: Ahi, Bhi, Blo) ----------------
__device__ __forceinline__ void load_chunk_async(uint32_t sbase, uint32_t stage, int c,
                                                 int rowA0, int rowB0, int tid) {
#pragma unroll
    for (int m = 0; m < 12; m++) {
        int u = tid + 256 * m;
        int t = u >> 10;            // 0: Ahi, 1: Bhi, 2: Blo
        int v = u & 1023;
        int r = v >> 3;             // row 0..127
        int i16 = v & 7;            // 16B group within 128B row
        int grow = ((t == 0) ? rowA0 : rowB0) + r;
        const __nv_bfloat16* base = (t == 2) ? g_lo : g_hi;
        const char* gp = (const char*)(base + (size_t)grow * DIM) + c * 128 + i16 * 16;
        uint32_t dst = sbase + stage * SM_STAGE + (uint32_t)t * SM_TILE
                     + (uint32_t)(r * 128) + (uint32_t)((i16 ^ (r & 7)) << 4);
        asm volatile("cp.async.cg.shared.global [%0], [%1], 16;" :: "r"(dst), "l"(gp));
    }
}

// ---------------- fused gram (HMMA, 2-product bf16 split) + RBF mixture ----------------
__global__ __launch_bounds__(256, 2) void mmd_mma_kernel() {
    extern __shared__ char smem[];
    const uint32_t sbase = smem_u32_of(smem);
    int tid = threadIdx.x;
    int wid = tid >> 5, lane = tid & 31;

    int rem = blockIdx.x, ti = 0;
    while (rem >= GRID_T - ti) { rem -= GRID_T - ti; ti++; }
    int tj = ti + rem;
    int rowA0 = ti * TILE, rowB0 = tj * TILE;

    float* sqA_s = (float*)(smem + SM_SQA);
    float* sqB_s = (float*)(smem + SM_SQB);
    if (tid < 128) sqA_s[tid] = g_sq[rowA0 + tid];
    else           sqB_s[tid - 128] = g_sq[rowB0 + (tid - 128)];

    // prologue: chunk 0 -> stage 0
    load_chunk_async(sbase, 0, 0, rowA0, rowB0, tid);
    asm volatile("cp.async.commit_group;" ::: "memory");

    // warp tiling: 2 (rows) x 4 (cols) warps; warp tile 64x32
    int wr = wid >> 2, wc = wid & 3;
    int rA = wr * 64 + (lane & 15);
    int kgA = lane >> 4;
    int xrA = rA & 7;
    uint32_t aAddr[4];
#pragma unroll
    for (int mi = 0; mi < 4; mi++)
        aAddr[mi] = sbase + (uint32_t)((rA + mi * 16) * 128);
    int nB = wc * 32 + (lane & 7) + ((lane >> 4) << 3);
    int kgB = (lane >> 3) & 1;
    int xrB = nB & 7;
    uint32_t bAddr[2];
#pragma unroll
    for (int nb = 0; nb < 2; nb++)
        bAddr[nb] = sbase + SM_TILE + (uint32_t)((nB + nb * 16) * 128);

    float acc[4][4][4];
#pragma unroll
    for (int i = 0; i < 4; i++)
#pragma unroll
        for (int j = 0; j < 4; j++)
#pragma unroll
            for (int e = 0; e < 4; e++) acc[i][j][e] = 0.f;

    for (int c = 0; c < NCHUNK; c++) {
        asm volatile("cp.async.wait_group 0;" ::: "memory");
        __syncthreads();
        // the barrier also proves all warps finished compute on chunk c-1,
        // so its stage (c+1)&1 is free to overwrite now
        if (c + 1 < NCHUNK) {
            load_chunk_async(sbase, (uint32_t)((c + 1) & 1), c + 1, rowA0, rowB0, tid);
            asm volatile("cp.async.commit_group;" ::: "memory");
        }
        uint32_t stoff = (uint32_t)(c & 1) * SM_STAGE;
#pragma unroll
        for (int s = 0; s < 4; s++) {
            uint32_t colA = (uint32_t)(((s * 2 + kgA) ^ xrA) << 4);
            uint32_t colB = (uint32_t)(((s * 2 + kgB) ^ xrB) << 4);
            uint32_t ah[4][4], bh[2][4], bl[2][4];
#pragma unroll
            for (int mi = 0; mi < 4; mi++)
                LDSM_X4(ah[mi], aAddr[mi] + stoff + colA);
#pragma unroll
            for (int nb = 0; nb < 2; nb++) {
                LDSM_X4(bh[nb], bAddr[nb] + stoff + colB);
                LDSM_X4(bl[nb], bAddr[nb] + stoff + colB + SM_TILE);
            }
#pragma unroll
            for (int mi = 0; mi < 4; mi++) {
#pragma unroll
                for (int ni = 0; ni < 4; ni++) {
                    int nb = ni >> 1, j = ni & 1;
                    MMA_BF16(acc[mi][ni], ah[mi], bh[nb][2 * j], bh[nb][2 * j + 1]);
                    MMA_BF16(acc[mi][ni], ah[mi], bl[nb][2 * j], bl[nb][2 * j + 1]);
                }
            }
        }
    }

    // epilogue: RBF mixture from register accumulators
    float coef = g_coef;
    float part = 0.f;
    int re = wr * 64 + (lane >> 2);
    int ce = wc * 32 + (lane & 3) * 2;
#pragma unroll
    for (int mi = 0; mi < 4; mi++) {
#pragma unroll
        for (int ni = 0; ni < 4; ni++) {
            int row = re + mi * 16;
            int col = ce + ni * 8;
#pragma unroll
            for (int e = 0; e < 4; e++) {
                float sA = sqA_s[row + ((e >> 1) << 3)];
                float sB = sqB_s[col + (e & 1)];
                float L2 = sA + sB - 2.f * acc[mi][ni][e];
                float t;
                asm("ex2.approx.ftz.f32 %0, %1;" : "=f"(t) : "f"(L2 * coef));
                float t2 = t * t, t4 = t2 * t2, t8 = t4 * t4, t16 = t8 * t8;
                part += t + t2 + t4 + t8 + t16;
            }
        }
    }

    float* red = (float*)(smem + SM_RED);
    red[tid] = part;
    __syncthreads();
#pragma unroll
    for (int o = 128; o; o >>= 1) {
        if (tid < o) red[tid] += red[tid + o];
        __syncthreads();
    }
    if (tid == 0) {
        float sign = ((ti < GRID_T / 2) == (tj < GRID_T / 2)) ? 1.f : -1.f;
        float wgt = (ti == tj) ? 1.f : 2.f;
        g_partials[blockIdx.x] = red[0] * sign * wgt;
    }
}

__global__ void reduce_kernel(float* __restrict__ out) {
    __shared__ double sh[256];
    int t = threadIdx.x;
    double a = 0.0;
    for (int i = t; i < NUM_TILES; i += 256) a += (double)g_partials[i];
    sh[t] = a; __syncthreads();
    for (int o = 128; o; o >>= 1) { if (t < o) sh[t] += sh[t + o]; __syncthreads(); }
    if (t == 0) out[0] = (float)(sh[0] / ((double)N_HALF * (double)N_HALF));
}

extern "C" void kernel_launch(void* const* d_in, const int* in_sizes, int n_in,
                              void* d_out, int out_size) {
    const float* src = (const float*)d_in[0];
    const float* tgt = (const float*)d_in[1];
    cudaFuncSetAttribute(mmd_mma_kernel, cudaFuncAttributeMaxDynamicSharedMemorySize,
                         SMEM_TOTAL);
    zero_colsum_kernel<<<2, 256>>>();
    prep_kernel<<<N_TOT / 8, 256>>>(src, tgt);
    bw_kernel<<<1, 256>>>();
    mmd_mma_kernel<<<NUM_TILES, 256, SMEM_TOTAL>>>();
    reduce_kernel<<<1, 256>>>((float*)d_out);
}

// round 6
// speedup vs baseline: 6.9717x; 1.6189x over previous
#include <cuda_runtime.h>
#include <cuda_bf16.h>
#include <stdint.h>

#define N_HALF 4096
#define N_TOT  8192
#define DIM    512
#define TILE   128
#define NCHUNK 8
#define GRID_T 64
#define NUM_TILES 2080

__device__ __nv_bfloat16 g_hi[(size_t)N_TOT * DIM];
__device__ float g_sq[N_TOT];
__device__ float g_colsum[DIM];
__device__ float g_coef;
__device__ float g_partials[NUM_TILES];

__device__ __forceinline__ uint32_t smem_u32_of(const void* p) {
    uint32_t a;
    asm("{ .reg .u64 t; cvta.to.shared.u64 t, %1; cvt.u32.u64 %0, t; }" : "=r"(a) : "l"(p));
    return a;
}

#define LDSM_X4(r, addr)                                                       \
    asm volatile("ldmatrix.sync.aligned.m8n8.x4.shared.b16 {%0,%1,%2,%3}, [%4];" \
        : "=r"((r)[0]), "=r"((r)[1]), "=r"((r)[2]), "=r"((r)[3]) : "r"(addr))

#define MMA_BF16(c, a, b0, b1)                                                 \
    asm volatile("mma.sync.aligned.m16n8k16.row.col.f32.bf16.bf16.f32 "        \
        "{%0,%1,%2,%3},{%4,%5,%6,%7},{%8,%9},{%0,%1,%2,%3};"                   \
        : "+f"((c)[0]), "+f"((c)[1]), "+f"((c)[2]), "+f"((c)[3])               \
        : "r"((a)[0]), "r"((a)[1]), "r"((a)[2]), "r"((a)[3]), "r"(b0), "r"(b1))

// ---------------- smem map (bytes) ----------------
// per stage: Ahi (16K) | Bhi (16K) = 32K; 3 stages; 2 CTAs/SM
#define SM_TILE    16384
#define SM_STAGE   32768
#define SM_SQA     98304
#define SM_SQB     (SM_SQA + 512)
#define SM_RED     (SM_SQB + 512)
#define SMEM_TOTAL (SM_RED + 1024)

// ---------------- preprocess: round to bf16, norms/colsums of ROUNDED data ----
__global__ void zero_colsum_kernel() {
    int i = blockIdx.x * blockDim.x + threadIdx.x;
    if (i < DIM) g_colsum[i] = 0.f;
}

__global__ __launch_bounds__(256) void prep_kernel(const float* __restrict__ src,
                                                   const float* __restrict__ tgt) {
    __shared__ float cs[DIM];
    int tid = threadIdx.x;
    for (int i = tid; i < DIM; i += 256) cs[i] = 0.f;
    __syncthreads();
    int warp = tid >> 5, lane = tid & 31;
    int row = blockIdx.x * 8 + warp;
    const float* p = (row < N_HALF) ? src + (size_t)row * DIM
                                    : tgt + (size_t)(row - N_HALF) * DIM;
    const float2* p2 = (const float2*)p;
    __nv_bfloat162* h2p = (__nv_bfloat162*)(g_hi + (size_t)row * DIM);
    float sq = 0.f;
#pragma unroll
    for (int i = 0; i < 8; i++) {
        int c = lane + 32 * i;
        float2 v = p2[c];
        __nv_bfloat16 hx = __float2bfloat16(v.x);
        __nv_bfloat16 hy = __float2bfloat16(v.y);
        float fx = __bfloat162float(hx);
        float fy = __bfloat162float(hy);
        sq += fx * fx + fy * fy;
        atomicAdd(&cs[2 * c], fx);
        atomicAdd(&cs[2 * c + 1], fy);
        __nv_bfloat162 h2; h2.x = hx; h2.y = hy;
        h2p[c] = h2;
    }
#pragma unroll
    for (int o = 16; o; o >>= 1) sq += __shfl_xor_sync(0xffffffffu, sq, o);
    if (lane == 0) g_sq[row] = sq;
    __syncthreads();
    for (int i = tid; i < DIM; i += 256) atomicAdd(&g_colsum[i], cs[i]);
}

__global__ void bw_kernel() {
    __shared__ double sh[256];
    int t = threadIdx.x;
    double acc = 0.0;
    for (int i = t; i < N_TOT; i += 256) acc += (double)g_sq[i];
    double acc2 = 0.0;
    for (int i = t; i < DIM; i += 256) { double c = (double)g_colsum[i]; acc2 += c * c; }
    sh[t] = acc; __syncthreads();
    for (int o = 128; o; o >>= 1) { if (t < o) sh[t] += sh[t + o]; __syncthreads(); }
    double sumsq = sh[0];
    __syncthreads();
    sh[t] = acc2; __syncthreads();
    for (int o = 128; o; o >>= 1) { if (t < o) sh[t] += sh[t + o]; __syncthreads(); }
    if (t == 0) {
        double ss = sh[0];
        double sumL2 = 2.0 * (double)N_TOT * sumsq - 2.0 * ss;
        double bw = sumL2 / ((double)N_TOT * (double)N_TOT - (double)N_TOT);
        g_coef = (float)(-1.4426950408889634 / (4.0 * bw));
    }
}

// ---------------- async tile loader (2 tiles: Ahi, Bhi) ----------------
__device__ __forceinline__ void load_chunk_async(uint32_t sbase, uint32_t stage, int c,
                                                 int rowA0, int rowB0, int tid) {
#pragma unroll
    for (int m = 0; m < 8; m++) {
        int u = tid + 256 * m;
        int t = u >> 10;            // 0: Ahi, 1: Bhi
        int v = u & 1023;
        int r = v >> 3;             // row 0..127
        int i16 = v & 7;            // 16B group within 128B row
        int grow = ((t == 0) ? rowA0 : rowB0) + r;
        const char* gp = (const char*)(g_hi + (size_t)grow * DIM) + c * 128 + i16 * 16;
        uint32_t dst = sbase + stage * SM_STAGE + (uint32_t)t * SM_TILE
                     + (uint32_t)(r * 128) + (uint32_t)((i16 ^ (r & 7)) << 4);
        asm volatile("cp.async.cg.shared.global [%0], [%1], 16;" :: "r"(dst), "l"(gp));
    }
}

// ---------------- fused gram (single-product bf16 HMMA) + RBF mixture --------
__global__ __launch_bounds__(256, 2) void mmd_mma_kernel() {
    extern __shared__ char smem[];
    const uint32_t sbase = smem_u32_of(smem);
    int tid = threadIdx.x;
    int wid = tid >> 5, lane = tid & 31;

    int rem = blockIdx.x, ti = 0;
    while (rem >= GRID_T - ti) { rem -= GRID_T - ti; ti++; }
    int tj = ti + rem;
    int rowA0 = ti * TILE, rowB0 = tj * TILE;

    float* sqA_s = (float*)(smem + SM_SQA);
    float* sqB_s = (float*)(smem + SM_SQB);
    if (tid < 128) sqA_s[tid] = g_sq[rowA0 + tid];
    else           sqB_s[tid - 128] = g_sq[rowB0 + (tid - 128)];

    // prologue: chunks 0,1 -> stages 0,1
    load_chunk_async(sbase, 0, 0, rowA0, rowB0, tid);
    asm volatile("cp.async.commit_group;" ::: "memory");
    load_chunk_async(sbase, 1, 1, rowA0, rowB0, tid);
    asm volatile("cp.async.commit_group;" ::: "memory");

    // warp tiling: 2 (rows) x 4 (cols) warps; warp tile 64x32
    int wr = wid >> 2, wc = wid & 3;
    int rA = wr * 64 + (lane & 15);
    int kgA = lane >> 4;
    int xrA = rA & 7;
    uint32_t aAddr[4];
#pragma unroll
    for (int mi = 0; mi < 4; mi++)
        aAddr[mi] = sbase + (uint32_t)((rA + mi * 16) * 128);
    int nB = wc * 32 + (lane & 7) + ((lane >> 4) << 3);
    int kgB = (lane >> 3) & 1;
    int xrB = nB & 7;
    uint32_t bAddr[2];
#pragma unroll
    for (int nb = 0; nb < 2; nb++)
        bAddr[nb] = sbase + SM_TILE + (uint32_t)((nB + nb * 16) * 128);

    float acc[4][4][4];
#pragma unroll
    for (int i = 0; i < 4; i++)
#pragma unroll
        for (int j = 0; j < 4; j++)
#pragma unroll
            for (int e = 0; e < 4; e++) acc[i][j][e] = 0.f;

    int stage = 0;
    for (int c = 0; c < NCHUNK; c++) {
        if (c + 1 < NCHUNK) asm volatile("cp.async.wait_group 1;" ::: "memory");
        else                asm volatile("cp.async.wait_group 0;" ::: "memory");
        __syncthreads();
        // barrier proves compute of chunk c-1 done => its stage (= (c+2)%3) is free
        if (c + 2 < NCHUNK) {
            int sn = stage + 2; if (sn >= 3) sn -= 3;
            load_chunk_async(sbase, (uint32_t)sn, c + 2, rowA0, rowB0, tid);
            asm volatile("cp.async.commit_group;" ::: "memory");
        }
        uint32_t stoff = (uint32_t)stage * SM_STAGE;
#pragma unroll
        for (int s = 0; s < 4; s++) {
            uint32_t colA = (uint32_t)(((s * 2 + kgA) ^ xrA) << 4);
            uint32_t colB = (uint32_t)(((s * 2 + kgB) ^ xrB) << 4);
            uint32_t ah[4][4], bh[2][4];
#pragma unroll
            for (int mi = 0; mi < 4; mi++)
                LDSM_X4(ah[mi], aAddr[mi] + stoff + colA);
#pragma unroll
            for (int nb = 0; nb < 2; nb++)
                LDSM_X4(bh[nb], bAddr[nb] + stoff + colB);
#pragma unroll
            for (int mi = 0; mi < 4; mi++) {
#pragma unroll
                for (int ni = 0; ni < 4; ni++) {
                    int nb = ni >> 1, j = ni & 1;
                    MMA_BF16(acc[mi][ni], ah[mi], bh[nb][2 * j], bh[nb][2 * j + 1]);
                }
            }
        }
        stage++; if (stage >= 3) stage = 0;
    }

    // epilogue: RBF mixture from register accumulators
    float coef = g_coef;
    float part = 0.f;
    int re = wr * 64 + (lane >> 2);
    int ce = wc * 32 + (lane & 3) * 2;
#pragma unroll
    for (int mi = 0; mi < 4; mi++) {
#pragma unroll
        for (int ni = 0; ni < 4; ni++) {
            int row = re + mi * 16;
            int col = ce + ni * 8;
#pragma unroll
            for (int e = 0; e < 4; e++) {
                float sA = sqA_s[row + ((e >> 1) << 3)];
                float sB = sqB_s[col + (e & 1)];
                float L2 = sA + sB - 2.f * acc[mi][ni][e];
                float t;
                asm("ex2.approx.ftz.f32 %0, %1;" : "=f"(t) : "f"(L2 * coef));
                float t2 = t * t, t4 = t2 * t2, t8 = t4 * t4, t16 = t8 * t8;
                part += t + t2 + t4 + t8 + t16;
            }
        }
    }

    float* red = (float*)(smem + SM_RED);
    red[tid] = part;
    __syncthreads();
#pragma unroll
    for (int o = 128; o; o >>= 1) {
        if (tid < o) red[tid] += red[tid + o];
        __syncthreads();
    }
    if (tid == 0) {
        float sign = ((ti < GRID_T / 2) == (tj < GRID_T / 2)) ? 1.f : -1.f;
        float wgt = (ti == tj) ? 1.f : 2.f;
        g_partials[blockIdx.x] = red[0] * sign * wgt;
    }
}

__global__ void reduce_kernel(float* __restrict__ out) {
    __shared__ double sh[256];
    int t = threadIdx.x;
    double a = 0.0;
    for (int i = t; i < NUM_TILES; i += 256) a += (double)g_partials[i];
    sh[t] = a; __syncthreads();
    for (int o = 128; o; o >>= 1) { if (t < o) sh[t] += sh[t + o]; __syncthreads(); }
    if (t == 0) out[0] = (float)(sh[0] / ((double)N_HALF * (double)N_HALF));
}

extern "C" void kernel_launch(void* const* d_in, const int* in_sizes, int n_in,
                              void* d_out, int out_size) {
    const float* src = (const float*)d_in[0];
    const float* tgt = (const float*)d_in[1];
    cudaFuncSetAttribute(mmd_mma_kernel, cudaFuncAttributeMaxDynamicSharedMemorySize,
                         SMEM_TOTAL);
    zero_colsum_kernel<<<2, 256>>>();
    prep_kernel<<<N_TOT / 8, 256>>>(src, tgt);
    bw_kernel<<<1, 256>>>();
    mmd_mma_kernel<<<NUM_TILES, 256, SMEM_TOTAL>>>();
    reduce_kernel<<<1, 256>>>((float*)d_out);
}